// round 2
// baseline (speedup 1.0000x reference)
#include <cuda_runtime.h>
#include <math.h>

#define Bn 128
#define Tn 512
#define Dn 256
#define Hn 512
#define G4 2048  // 4*H

// Scratch: zx[t][b][g]  (512 MB), h ping-pong, c state
__device__ float g_zx[(size_t)Tn * Bn * G4];
__device__ float g_h[2][Bn * Hn];
__device__ float g_c[Bn * Hn];

// ---------------------------------------------------------------------------
// init: zero h[0] and c
// ---------------------------------------------------------------------------
__global__ void init_kernel() {
    int i = blockIdx.x * blockDim.x + threadIdx.x;
    if (i < Bn * Hn) {
        g_h[0][i] = 0.0f;
        g_c[i] = 0.0f;
    }
}

// ---------------------------------------------------------------------------
// zx = x @ Wx + b   ->  g_zx[t][b][g]
// A = x as [B*T, D] row-major (row m = b*T + t), B = Wx [D, 4H]
// 64x64 tile, KT=16, 256 threads, 4x4 micro-tile
// ---------------------------------------------------------------------------
__global__ __launch_bounds__(256) void zx_kernel(
    const float* __restrict__ x,
    const float* __restrict__ Wx,
    const float* __restrict__ bias)
{
    __shared__ __align__(16) float As[16][68];  // [k][m], padded
    __shared__ __align__(16) float Bs[16][64];  // [k][n]

    int tid = threadIdx.x;
    int tx = tid & 15;        // col group
    int ty = tid >> 4;        // row group
    int mbase = blockIdx.y * 64;
    int nbase = blockIdx.x * 64;

    float acc[4][4] = {};

    for (int kb = 0; kb < Dn; kb += 16) {
        // load A tile (64 rows x 16 k) transposed into As[k][m]
        {
            int ka = tid & 15;
            int ma = tid >> 4;
            #pragma unroll
            for (int p = 0; p < 4; p++) {
                int m = ma + p * 16;
                As[ka][m] = x[(size_t)(mbase + m) * Dn + kb + ka];
            }
        }
        // load B tile (16 k x 64 n)
        #pragma unroll
        for (int p = 0; p < 4; p++) {
            int idx = p * 256 + tid;
            int kk = idx >> 6;
            int c  = idx & 63;
            Bs[kk][c] = Wx[(size_t)(kb + kk) * G4 + nbase + c];
        }
        __syncthreads();

        #pragma unroll
        for (int kk = 0; kk < 16; kk++) {
            float4 av = *reinterpret_cast<const float4*>(&As[kk][ty * 4]);
            float4 bv = *reinterpret_cast<const float4*>(&Bs[kk][tx * 4]);
            float a[4] = {av.x, av.y, av.z, av.w};
            float bb[4] = {bv.x, bv.y, bv.z, bv.w};
            #pragma unroll
            for (int v = 0; v < 4; v++)
                #pragma unroll
                for (int u = 0; u < 4; u++)
                    acc[v][u] += a[v] * bb[u];
        }
        __syncthreads();
    }

    // epilogue: add bias, scatter to zx[t][b][g]
    #pragma unroll
    for (int v = 0; v < 4; v++) {
        int m = mbase + ty * 4 + v;   // m = b*T + t
        int b = m >> 9;               // /512
        int t = m & 511;
        size_t base = ((size_t)t * Bn + b) * G4 + nbase + tx * 4;
        #pragma unroll
        for (int u = 0; u < 4; u++) {
            g_zx[base + u] = acc[v][u] + bias[nbase + tx * 4 + u];
        }
    }
}

// ---------------------------------------------------------------------------
// One LSTM step:
//   z = zx[t] + h_prev @ Wh ;  gates ;  c,h update ;  write outputs
// grid: (H/32 = 16 j-tiles, B/16 = 8 m-tiles), 256 threads
// Each thread: 2 batch rows x 1 j x 4 gates
// ---------------------------------------------------------------------------
__global__ __launch_bounds__(256) void step_kernel(
    const float* __restrict__ Wh,
    float* __restrict__ out,
    int t)
{
    const float* __restrict__ hprev = g_h[t & 1];
    float* __restrict__ hnext = g_h[(t + 1) & 1];

    __shared__ __align__(16) float As[32][17];   // [k][m], BM=16, padded
    __shared__ __align__(16) float Bs[32][128];  // [k][gate*32 + jj]

    int tid = threadIdx.x;
    int tx = tid & 31;     // j within tile
    int ty = tid >> 5;     // row group 0..7
    int j0 = blockIdx.x * 32;
    int m0 = blockIdx.y * 16;

    float acc[2][4] = {};  // [row][gate]

    for (int kb = 0; kb < Hn; kb += 32) {
        // load h tile: h[m0+m][kb+k] -> As[k][m]  (16x32)
        {
            int k = tid & 31;
            int m = tid >> 5;   // 0..7
            As[k][m]     = hprev[(m0 + m) * Hn + kb + k];
            As[k][m + 8] = hprev[(m0 + m + 8) * Hn + kb + k];
        }
        // load Wh tile: Wh[kb+k][gate*512 + j0 + jj] -> Bs[k][gate*32+jj]
        #pragma unroll
        for (int p = 0; p < 4; p++) {
            int vidx = p * 256 + tid;   // 0..1023, one float4 each
            int k  = vidx >> 5;
            int c  = (vidx & 31) * 4;
            int gate = c >> 5;
            int jj   = c & 31;
            float4 w = *reinterpret_cast<const float4*>(
                &Wh[(size_t)(kb + k) * G4 + gate * Hn + j0 + jj]);
            *reinterpret_cast<float4*>(&Bs[k][c]) = w;
        }
        __syncthreads();

        #pragma unroll
        for (int kk = 0; kk < 32; kk++) {
            float a0 = As[kk][ty * 2];
            float a1 = As[kk][ty * 2 + 1];
            #pragma unroll
            for (int g = 0; g < 4; g++) {
                float bg = Bs[kk][g * 32 + tx];
                acc[0][g] += a0 * bg;
                acc[1][g] += a1 * bg;
            }
        }
        __syncthreads();
    }

    // epilogue: gates + state update + output write
    int j = j0 + tx;
    size_t zxbase = ((size_t)t * Bn) * G4;

    #pragma unroll
    for (int r = 0; r < 2; r++) {
        int m = m0 + ty * 2 + r;
        const float* zrow = &g_zx[zxbase + (size_t)m * G4];
        float zi = acc[r][0] + zrow[0 * Hn + j];
        float zf = acc[r][1] + zrow[1 * Hn + j];
        float zg = acc[r][2] + zrow[2 * Hn + j];
        float zo = acc[r][3] + zrow[3 * Hn + j];

        float ig = 1.0f / (1.0f + __expf(-zi));
        float fg = 1.0f / (1.0f + __expf(-zf));
        float gg = tanhf(zg);
        float og = 1.0f / (1.0f + __expf(-zo));

        int sidx = m * Hn + j;
        float cold = g_c[sidx];
        float cnew = fg * cold + ig * gg;
        float hnew = og * tanhf(cnew);

        g_c[sidx] = cnew;
        hnext[sidx] = hnew;
        out[((size_t)m * Tn + t) * Hn + j] = hnew;

        if (t == Tn - 1) {
            size_t tail = (size_t)Bn * Tn * Hn;
            out[tail + (size_t)m * Hn + j] = hnew;                       // hT
            out[tail + (size_t)Bn * Hn + (size_t)m * Hn + j] = cnew;     // cT
        }
    }
}

// ---------------------------------------------------------------------------
extern "C" void kernel_launch(void* const* d_in, const int* in_sizes, int n_in,
                              void* d_out, int out_size) {
    const float* x  = (const float*)d_in[0];   // [B,T,D]
    const float* Wx = (const float*)d_in[1];   // [D,4H]
    const float* Wh = (const float*)d_in[2];   // [H,4H]
    const float* b  = (const float*)d_in[3];   // [4H]
    float* out = (float*)d_out;

    // zero h[0], c
    init_kernel<<<(Bn * Hn + 255) / 256, 256>>>();

    // input projection: zx = x @ Wx + b
    dim3 zgrid(G4 / 64, (Bn * Tn) / 64);   // (32, 1024)
    zx_kernel<<<zgrid, 256>>>(x, Wx, b);

    // recurrence
    dim3 sgrid(Hn / 32, Bn / 16);          // (16, 8)
    for (int t = 0; t < Tn; t++) {
        step_kernel<<<sgrid, 256>>>(Wh, out, t);
    }
}